// round 5
// baseline (speedup 1.0000x reference)
#include <cuda_runtime.h>

#define SS 512
#define NUNITS 9
#define DSTRIDE 544   // 512 data + 32 zero pad; 544*4 = 2176 B = 136 x 16B chunks
#define MAXB 128
#define NCHUNK (DSTRIDE * 4 / 16)   // 136

__device__ float g_diag[MAXB * DSTRIDE];
__device__ float g_bias[SS * SS];

// Fused prep. Diag-gather blocks take the LOW block indices so the
// latency-bound gather starts first; bias streaming overlaps behind it.
__global__ void prep_kernel(const float* __restrict__ in,
                            const float* __restrict__ bb,
                            int B, int ndiag_blocks) {
    if (blockIdx.x < (unsigned)ndiag_blocks) {
        int idx = blockIdx.x * blockDim.x + threadIdx.x;
        int total = B * DSTRIDE;
        if (idx >= total) return;
        int b = idx / DSTRIDE;
        int j = idx - b * DSTRIDE;
        float v = 0.0f;
        if (j < SS) v = __ldg(in + (size_t)b * SS * SS + (size_t)j * (SS + 1));
        g_diag[idx] = v;
    } else {
        int t4 = (blockIdx.x - ndiag_blocks) * blockDim.x + threadIdx.x;
        if (t4 >= (SS * SS) / 4) return;
        const float4* bp = (const float4*)(bb + (size_t)t4 * 36);
        float v[36];
#pragma unroll
        for (int k = 0; k < 9; k++) {
            float4 q = bp[k];
            v[k * 4 + 0] = q.x; v[k * 4 + 1] = q.y;
            v[k * 4 + 2] = q.z; v[k * 4 + 3] = q.w;
        }
        float4 s;
        float* sp = (float*)&s;
#pragma unroll
        for (int jj = 0; jj < 4; jj++) {
            float acc = 0.0f;
#pragma unroll
            for (int t = 0; t < 9; t++) acc += v[jj * 9 + t];
            sp[jj] = acc;
        }
        *(float4*)(g_bias + (size_t)t4 * 4) = s;
    }
}

__device__ __forceinline__ void stage_row(float* sbuf, const float* grow, int tid) {
    // 136 x 16B chunks: threads 0..127 take one, threads 0..7 take a second.
    unsigned saddr0 = (unsigned)__cvta_generic_to_shared(sbuf + tid * 4);
    asm volatile("cp.async.ca.shared.global [%0], [%1], 16;\n"
                 :: "r"(saddr0), "l"(grow + tid * 4) : "memory");
    if (tid < NCHUNK - 128) {
        unsigned saddr1 = (unsigned)__cvta_generic_to_shared(sbuf + (128 + tid) * 4);
        asm volatile("cp.async.ca.shared.global [%0], [%1], 16;\n"
                     :: "r"(saddr1), "l"(grow + (128 + tid) * 4) : "memory");
    }
    asm volatile("cp.async.commit_group;\n" ::: "memory");
}

// Main kernel: 1 i-row x 1 j-quad per thread; diag rows double-buffered in
// smem via cp.async so every compute read is a fixed-latency LDS hit.
__global__ __launch_bounds__(128, 6)
void cnn_kernel(const float* __restrict__ w,
                float* __restrict__ out,
                int B, int bper) {
    __shared__ float sdiag[2][DSTRIDE];

    int i  = blockIdx.x;          // 0..511
    int tid = threadIdx.x;
    int j0 = tid << 2;            // 0,4,...,508
    int b0 = blockIdx.y * bper;
    int b1 = b0 + bper;
    if (b1 > B) b1 = B;
    if (b0 >= b1) return;

    // ---- prologue: start staging batch b0, then load weights/bias ----
    stage_row(sdiag[0], g_diag + (size_t)b0 * DSTRIDE, tid);

    float wv[36];
    const float4* wp4 = (const float4*)(w + ((size_t)i * SS + j0) * NUNITS);
#pragma unroll
    for (int k = 0; k < 9; k++) {
        float4 q = wp4[k];
        wv[k * 4 + 0] = q.x; wv[k * 4 + 1] = q.y;
        wv[k * 4 + 2] = q.z; wv[k * 4 + 3] = q.w;
    }
#pragma unroll
    for (int n = 0; n < 36; n++) {
        int t = n % 9;                         // compile-time per n
        wv[n] *= (i + (t / 3) < SS) ? 9.0f : 0.0f;
    }
    float4 bias4 = *(const float4*)(g_bias + (size_t)i * SS + j0);

    float* op = out + (size_t)b0 * (SS * SS) + (size_t)i * SS + j0;

    for (int b = b0; b < b1; ++b) {
        int k = (b - b0) & 1;
        if (b + 1 < b1) {
            stage_row(sdiag[k ^ 1], g_diag + (size_t)(b + 1) * DSTRIDE, tid);
            asm volatile("cp.async.wait_group 1;\n" ::: "memory");
        } else {
            asm volatile("cp.async.wait_group 0;\n" ::: "memory");
        }
        __syncthreads();   // sdiag[k] fully staged, visible to all warps

        const float4* sp = (const float4*)(sdiag[k] + j0);
        float4 c0 = sp[0], c1 = sp[1], c2 = sp[2];
        float d[12] = {c0.x, c0.y, c0.z, c0.w,
                       c1.x, c1.y, c1.z, c1.w,
                       c2.x, c2.y, c2.z, c2.w};

        float s0 = bias4.x, s1 = bias4.y, s2 = bias4.z, s3 = bias4.w;
#pragma unroll
        for (int t = 0; t < 9; t++) {
            s0 = fmaf(d[t],     wv[t],      s0);
            s1 = fmaf(d[t + 1], wv[9 + t],  s1);
            s2 = fmaf(d[t + 2], wv[18 + t], s2);
            s3 = fmaf(d[t + 3], wv[27 + t], s3);
        }
        float4 o; o.x = s0; o.y = s1; o.z = s2; o.w = s3;
        *(float4*)op = o;
        op += SS * SS;

        __syncthreads();   // all reads of sdiag[k] done before it is restaged
    }
}

extern "C" void kernel_launch(void* const* d_in, const int* in_sizes, int n_in,
                              void* d_out, int out_size) {
    const float* in = (const float*)d_in[0];   // inputs (B,512,512,1) f32
    const float* w  = (const float*)d_in[1];   // w (512*512*9,) f32
    const float* bb = (const float*)d_in[2];   // b (512*512*9,) f32
    float* out = (float*)d_out;                // (B, 512*512) f32

    int B = in_sizes[0] / (SS * SS);
    if (B > MAXB) B = MAXB;

    {
        int ndiag_blocks = (B * DSTRIDE + 255) / 256;          // ~213
        int nbias_blocks = ((SS * SS) / 4 + 255) / 256;        // 256
        prep_kernel<<<ndiag_blocks + nbias_blocks, 256>>>(in, bb, B, ndiag_blocks);
    }

    const int NSLICE = 5;
    int bper = (B + NSLICE - 1) / NSLICE;
    dim3 grid(SS, NSLICE);                     // 2560 blocks
    cnn_kernel<<<grid, 128>>>(w, out, B, bper);
}

// round 6
// speedup vs baseline: 1.1431x; 1.1431x over previous
#include <cuda_runtime.h>

#define SS 512
#define NUNITS 9
#define DSTRIDE 520   // 512 data + 8 zero pad; multiple of 4 for float4 rows
#define MAXB 128

__device__ float g_diag[MAXB * DSTRIDE];
__device__ float g_bias[SS * SS];

// Fused prep. Diag gather first (latency-bound, MLP=4 per thread), bias
// reduction blocks stream behind it.
__global__ void prep_kernel(const float* __restrict__ in,
                            const float* __restrict__ bb,
                            int B, int ndiag_blocks) {
    if (blockIdx.x < (unsigned)ndiag_blocks) {
        // each thread: one j, FOUR batches -> 4 independent strided loads
        int idx = blockIdx.x * blockDim.x + threadIdx.x;
        int bq = idx / DSTRIDE;
        int j  = idx - bq * DSTRIDE;
        int b4 = bq * 4;
        if (b4 >= B) return;
        float v[4] = {0.f, 0.f, 0.f, 0.f};
        bool jin = (j < SS);
#pragma unroll
        for (int k = 0; k < 4; k++) {
            if (jin && b4 + k < B)
                v[k] = __ldg(in + (size_t)(b4 + k) * SS * SS + (size_t)j * (SS + 1));
        }
#pragma unroll
        for (int k = 0; k < 4; k++) {
            if (b4 + k < B) g_diag[(size_t)(b4 + k) * DSTRIDE + j] = v[k];
        }
    } else {
        int t4 = (blockIdx.x - ndiag_blocks) * blockDim.x + threadIdx.x;
        if (t4 >= (SS * SS) / 4) return;
        const float4* bp = (const float4*)(bb + (size_t)t4 * 36);
        float v[36];
#pragma unroll
        for (int k = 0; k < 9; k++) {
            float4 q = bp[k];
            v[k * 4 + 0] = q.x; v[k * 4 + 1] = q.y;
            v[k * 4 + 2] = q.z; v[k * 4 + 3] = q.w;
        }
        float4 s;
        float* sp = (float*)&s;
#pragma unroll
        for (int jj = 0; jj < 4; jj++) {
            float acc = 0.0f;
#pragma unroll
            for (int t = 0; t < 9; t++) acc += v[jj * 9 + t];
            sp[jj] = acc;
        }
        *(float4*)(g_bias + (size_t)t4 * 4) = s;
    }
}

// Main kernel: 1 i-row x 1 j-quad per thread, TWO batches per iteration for
// doubled memory-level parallelism (6 independent LDG.128 in flight).
__global__ __launch_bounds__(128, 5)
void cnn_kernel(const float* __restrict__ w,
                float* __restrict__ out,
                int B, int bper) {
    int i  = blockIdx.x;          // 0..511
    int j0 = threadIdx.x << 2;    // 0,4,...,508
    int b0 = blockIdx.y * bper;
    int b1 = b0 + bper;
    if (b1 > B) b1 = B;
    if (b0 >= b1) return;

    // ---- prologue: 9x LDG.128 weights + 1x LDG.128 bias sums ----
    float wv[36];
    const float4* wp4 = (const float4*)(w + ((size_t)i * SS + j0) * NUNITS);
#pragma unroll
    for (int k = 0; k < 9; k++) {
        float4 q = wp4[k];
        wv[k * 4 + 0] = q.x; wv[k * 4 + 1] = q.y;
        wv[k * 4 + 2] = q.z; wv[k * 4 + 3] = q.w;
    }
#pragma unroll
    for (int n = 0; n < 36; n++) {
        int t = n % 9;                          // compile-time per n
        wv[n] *= (i + (t / 3) < SS) ? 9.0f : 0.0f;
    }
    float4 bias4 = *(const float4*)(g_bias + (size_t)i * SS + j0);

    const float* dbase = g_diag + (size_t)b0 * DSTRIDE + j0;
    float* op = out + (size_t)b0 * (SS * SS) + (size_t)i * SS + j0;

    int b = b0;
    // ---- paired batches: 6 independent LDG.128 per iteration ----
    for (; b + 1 < b1; b += 2) {
        const float4* dqa = (const float4*)dbase;
        const float4* dqb = (const float4*)(dbase + DSTRIDE);
        float4 c0 = dqa[0], c1 = dqa[1], c2 = dqa[2];
        float4 f0 = dqb[0], f1 = dqb[1], f2 = dqb[2];

        float da[12] = {c0.x, c0.y, c0.z, c0.w,
                        c1.x, c1.y, c1.z, c1.w,
                        c2.x, c2.y, c2.z, c2.w};
        float db[12] = {f0.x, f0.y, f0.z, f0.w,
                        f1.x, f1.y, f1.z, f1.w,
                        f2.x, f2.y, f2.z, f2.w};

        float a0 = bias4.x, a1 = bias4.y, a2 = bias4.z, a3 = bias4.w;
        float e0 = bias4.x, e1 = bias4.y, e2 = bias4.z, e3 = bias4.w;
#pragma unroll
        for (int t = 0; t < 9; t++) {
            a0 = fmaf(da[t],     wv[t],      a0);
            a1 = fmaf(da[t + 1], wv[9 + t],  a1);
            a2 = fmaf(da[t + 2], wv[18 + t], a2);
            a3 = fmaf(da[t + 3], wv[27 + t], a3);
            e0 = fmaf(db[t],     wv[t],      e0);
            e1 = fmaf(db[t + 1], wv[9 + t],  e1);
            e2 = fmaf(db[t + 2], wv[18 + t], e2);
            e3 = fmaf(db[t + 3], wv[27 + t], e3);
        }
        float4 oa; oa.x = a0; oa.y = a1; oa.z = a2; oa.w = a3;
        float4 ob; ob.x = e0; ob.y = e1; ob.z = e2; ob.w = e3;
        *(float4*)op            = oa;
        *(float4*)(op + SS * SS) = ob;

        dbase += 2 * DSTRIDE;
        op += 2 * (SS * SS);
    }
    // ---- tail (odd slice length) ----
    if (b < b1) {
        const float4* dqa = (const float4*)dbase;
        float4 c0 = dqa[0], c1 = dqa[1], c2 = dqa[2];
        float da[12] = {c0.x, c0.y, c0.z, c0.w,
                        c1.x, c1.y, c1.z, c1.w,
                        c2.x, c2.y, c2.z, c2.w};
        float a0 = bias4.x, a1 = bias4.y, a2 = bias4.z, a3 = bias4.w;
#pragma unroll
        for (int t = 0; t < 9; t++) {
            a0 = fmaf(da[t],     wv[t],      a0);
            a1 = fmaf(da[t + 1], wv[9 + t],  a1);
            a2 = fmaf(da[t + 2], wv[18 + t], a2);
            a3 = fmaf(da[t + 3], wv[27 + t], a3);
        }
        float4 oa; oa.x = a0; oa.y = a1; oa.z = a2; oa.w = a3;
        *(float4*)op = oa;
    }
}

extern "C" void kernel_launch(void* const* d_in, const int* in_sizes, int n_in,
                              void* d_out, int out_size) {
    const float* in = (const float*)d_in[0];   // inputs (B,512,512,1) f32
    const float* w  = (const float*)d_in[1];   // w (512*512*9,) f32
    const float* bb = (const float*)d_in[2];   // b (512*512*9,) f32
    float* out = (float*)d_out;                // (B, 512*512) f32

    int B = in_sizes[0] / (SS * SS);
    if (B > MAXB) B = MAXB;

    {
        int bq = (B + 3) / 4;                                   // batch quads
        int ndiag_threads = bq * DSTRIDE;
        int ndiag_blocks = (ndiag_threads + 255) / 256;         // ~53
        int nbias_blocks = ((SS * SS) / 4 + 255) / 256;         // 256
        prep_kernel<<<ndiag_blocks + nbias_blocks, 256>>>(in, bb, B, ndiag_blocks);
    }

    const int NSLICE = 5;
    int bper = (B + NSLICE - 1) / NSLICE;
    dim3 grid(SS, NSLICE);                     // 2560 blocks
    cnn_kernel<<<grid, 128>>>(w, out, B, bper);
}